// round 14
// baseline (speedup 1.0000x reference)
#include <cuda_runtime.h>

#define DIM     1024
#define NPAIRS  512
#define NLAYER  10
#define NACTIVE 2044   // params for layers 1..9: 2*sum(DIM>>l, l=1..9)

// 256-bit x load with L2::evict_last — on sm_103a ptxas this hint is only
// legal on .v8.b32/.v4.b64 (LDG.256). Pins the 128MB x array in the 126MB L2
// across graph replays so steady-state reads mostly hit L2.
struct f8 { float4 lo, hi; };
__device__ __forceinline__ f8 ld_x256(const float* p) {
    f8 v;
    asm volatile("ld.global.nc.L2::evict_last.v8.b32 "
                 "{%0,%1,%2,%3,%4,%5,%6,%7}, [%8];"
                 : "=f"(v.lo.x), "=f"(v.lo.y), "=f"(v.lo.z), "=f"(v.lo.w),
                   "=f"(v.hi.x), "=f"(v.hi.y), "=f"(v.hi.z), "=f"(v.hi.w)
                 : "l"(p));
    return v;
}

// Single kernel, grid = rows/8, 8 rows per CTA (warp-per-row).
//
// Math: with base point 0 both Mobius maps are radial scalings
//   log0(x) = atanh(|x|)/|x| x,  exp0(v) = tanh(|v|)/|v| v,
// and the butterfly always pairs adjacent elements (2k,2k+1), acting as
// [[a,b],[-b,a]] = complex multiply by (a - ib): one composite W_k per pair,
//   |butterfly(u)|^2 = s1^2 * sum_k |W_k|^2 (x_{2k}^2 + x_{2k+1}^2).
//
// Two-pass row processing keeps register pressure low (no x array live across
// the reduction); pass 2 re-reads x from L1/L2. Row is walked in 32B chunks
// (4 LDG.256 per lane per pass). Stores are __stcs (evict-first streaming)
// so the write stream doesn't displace the pinned x.
__global__ void __launch_bounds__(256, 4)
hyper_butterfly_2pass(const float* __restrict__ x,
                      const float* __restrict__ params,
                      float* __restrict__ out) {
    __shared__ __align__(16) float buf[2048];      // 8 KB, reused

    const int t    = threadIdx.x;
    const int warp = t >> 5;
    const int lane = t & 31;

    // ── Prologue A: coalesced batch-load of active params.
#pragma unroll
    for (int j = 0; j < 8; ++j) {
        int i = t + 256 * j;
        if (i < NACTIVE) buf[i] = params[2 * DIM + i];
    }
    __syncthreads();

    // ── Prologue B: compose W for pairs t and t+256, keep in registers.
    float A[2], B[2];
#pragma unroll
    for (int h = 0; h < 2; ++h) {
        const int k = t + h * 256;
        float a0 = 1.0f, b0 = 0.0f;
        int off = 0;
#pragma unroll
        for (int l = 1; l < NLAYER; ++l) {
            const int blk = k >> (l - 1);
            const float a = buf[off + 2 * blk];
            const float b = buf[off + 2 * blk + 1];
            const float na = a0 * a + b0 * b;      // (a0+ib0)*(a-ib)
            const float nb = b0 * a - a0 * b;
            a0 = na; b0 = nb;
            off += 2 * (DIM >> l);
        }
        A[h] = a0; B[h] = b0;
    }
    __syncthreads();   // all param reads done before buffer reuse

    // ── Prologue C: write W tables into the reused buffer.
    //   buf[0..1023]    = float2 W_k   (pair k at float2 index k)
    //   buf[1024..1535] = |W_k|^2      (pair k at index 1024+k)
#pragma unroll
    for (int h = 0; h < 2; ++h) {
        const int k = t + h * 256;
        reinterpret_cast<float2*>(buf)[k] = make_float2(A[h], B[h]);
        buf[1024 + k] = A[h] * A[h] + B[h] * B[h];
    }
    __syncthreads();

    const float4* __restrict__ sW4 = reinterpret_cast<const float4*>(buf);        // 2 pairs / entry
    const float4* __restrict__ sZ4 = reinterpret_cast<const float4*>(buf + 1024); // 4 pairs / entry

    const int row = (blockIdx.x << 3) + warp;
    const float* __restrict__ xrow = x + (size_t)row * DIM;
    float4* __restrict__ orow      = reinterpret_cast<float4*>(out + (size_t)row * DIM);

    // ── Pass 1: stream x in 32B chunks (chunk c = lane + 32*j covers pairs
    //    4c..4c+3), accumulate both norms.
    float r0 = 0.0f, r1 = 0.0f;
#pragma unroll
    for (int j = 0; j < 4; ++j) {
        const int c = lane + 32 * j;
        const f8 v = ld_x256(xrow + 8 * c);
        const float4 wz = sZ4[c];
        const float q0 = v.lo.x * v.lo.x + v.lo.y * v.lo.y;
        const float q1 = v.lo.z * v.lo.z + v.lo.w * v.lo.w;
        const float q2 = v.hi.x * v.hi.x + v.hi.y * v.hi.y;
        const float q3 = v.hi.z * v.hi.z + v.hi.w * v.hi.w;
        r0 += (q0 + q1) + (q2 + q3);
        r1 += wz.x * q0 + wz.y * q1 + wz.z * q2 + wz.w * q3;
    }

    // Warp butterfly reduce both sums; every lane gets the totals.
#pragma unroll
    for (int o = 16; o; o >>= 1) {
        r0 += __shfl_xor_sync(0xffffffffu, r0, o);
        r1 += __shfl_xor_sync(0xffffffffu, r1, o);
    }

    const float n  = sqrtf(r0);
    const float s1 = atanhf(n) / fmaxf(n, 1e-12f);
    const float m  = s1 * sqrtf(r1);
    const float s  = s1 * tanhf(m) / fmaxf(m, 1e-12f);

    // ── Pass 2: reload (L2 hit), rotate, scale, streaming-store.
#pragma unroll
    for (int j = 0; j < 4; ++j) {
        const int c = lane + 32 * j;
        const f8 v = ld_x256(xrow + 8 * c);
        const float4 w0 = sW4[2 * c];       // pairs 4c, 4c+1
        const float4 w1 = sW4[2 * c + 1];   // pairs 4c+2, 4c+3
        float4 o0, o1;
        o0.x = s * (w0.x * v.lo.x - w0.y * v.lo.y);
        o0.y = s * (w0.x * v.lo.y + w0.y * v.lo.x);
        o0.z = s * (w0.z * v.lo.z - w0.w * v.lo.w);
        o0.w = s * (w0.z * v.lo.w + w0.w * v.lo.z);
        o1.x = s * (w1.x * v.hi.x - w1.y * v.hi.y);
        o1.y = s * (w1.x * v.hi.y + w1.y * v.hi.x);
        o1.z = s * (w1.z * v.hi.z - w1.w * v.hi.w);
        o1.w = s * (w1.z * v.hi.w + w1.w * v.hi.z);
        __stcs(orow + 2 * c,     o0);   // evict-first: don't displace x
        __stcs(orow + 2 * c + 1, o1);
    }
}

extern "C" void kernel_launch(void* const* d_in, const int* in_sizes, int n_in,
                              void* d_out, int out_size) {
    const float* x      = (const float*)d_in[0];
    const float* params = (const float*)d_in[1];
    float* out          = (float*)d_out;

    const int rows = in_sizes[0] / DIM;   // 32768
    hyper_butterfly_2pass<<<rows >> 3, 256>>>(x, params, out);
}

// round 15
// speedup vs baseline: 1.1539x; 1.1539x over previous
#include <cuda_runtime.h>

#define DIM     1024
#define NPAIRS  512
#define NLAYER  10
#define NACTIVE 2044   // params for layers 1..9: 2*sum(DIM>>l, l=1..9)

// Single kernel, grid = rows/8, 8 rows per CTA (warp-per-row).
//
// Math: with base point 0 both Mobius maps are radial scalings
//   log0(x) = atanh(|x|)/|x| x,  exp0(v) = tanh(|v|)/|v| v,
// and the butterfly always pairs adjacent elements (2k,2k+1), acting as
// [[a,b],[-b,a]] = complex multiply by (a - ib): one composite W_k per pair,
//   |butterfly(u)|^2 = s1^2 * sum_k |W_k|^2 (x_{2k}^2 + x_{2k+1}^2).
//
// This is the proven R11 configuration (45.3us best) with ONE delta:
// output stores use __stcs (evict-first streaming). The out write stream
// (128MB/replay) is what displaces x from L2; evict-first stores raise x's
// natural L2 residency across graph replays without the pinning pathology
// that sank the R14 evict_last experiment (sticky 128MB > 126MB L2 thrash).
__global__ void __launch_bounds__(256, 4)
hyper_butterfly_2pass(const float* __restrict__ x,
                      const float* __restrict__ params,
                      float* __restrict__ out) {
    __shared__ __align__(16) float buf[2048];      // 8 KB, reused

    const int t    = threadIdx.x;
    const int warp = t >> 5;
    const int lane = t & 31;

    // ── Prologue A: coalesced batch-load of active params.
#pragma unroll
    for (int j = 0; j < 8; ++j) {
        int i = t + 256 * j;
        if (i < NACTIVE) buf[i] = params[2 * DIM + i];
    }
    __syncthreads();

    // ── Prologue B: compose W for pairs t and t+256, keep in registers.
    float A[2], B[2];
#pragma unroll
    for (int h = 0; h < 2; ++h) {
        const int k = t + h * 256;
        float a0 = 1.0f, b0 = 0.0f;
        int off = 0;
#pragma unroll
        for (int l = 1; l < NLAYER; ++l) {
            const int blk = k >> (l - 1);
            const float a = buf[off + 2 * blk];
            const float b = buf[off + 2 * blk + 1];
            const float na = a0 * a + b0 * b;      // (a0+ib0)*(a-ib)
            const float nb = b0 * a - a0 * b;
            a0 = na; b0 = nb;
            off += 2 * (DIM >> l);
        }
        A[h] = a0; B[h] = b0;
    }
    __syncthreads();   // all param reads done before buffer reuse

    // ── Prologue C: write W tables into the reused buffer.
    //   buf[0..1023]    = float2 W_k (as float4 per 2-pair chunk)
    //   buf[1024..1535] = |W_k|^2 (as float2 per chunk)
#pragma unroll
    for (int h = 0; h < 2; ++h) {
        const int k = t + h * 256;
        reinterpret_cast<float2*>(buf)[k] = make_float2(A[h], B[h]);
        buf[1024 + k] = A[h] * A[h] + B[h] * B[h];
    }
    __syncthreads();

    const float4* __restrict__ sW4 = reinterpret_cast<const float4*>(buf);
    const float2* __restrict__ sZ  = reinterpret_cast<const float2*>(buf + 1024);

    const int row = (blockIdx.x << 3) + warp;
    const float4* __restrict__ xr = reinterpret_cast<const float4*>(x + (size_t)row * DIM);
    float4* __restrict__ orow     = reinterpret_cast<float4*>(out + (size_t)row * DIM);

    // ── Pass 1: stream x, accumulate both norms. No persistent x registers.
    float r0 = 0.0f, r1 = 0.0f;
#pragma unroll
    for (int j = 0; j < 8; ++j) {
        const float4 xv = xr[lane + 32 * j];
        const float2 wz = sZ[lane + 32 * j];
        const float q0 = xv.x * xv.x + xv.y * xv.y;
        const float q1 = xv.z * xv.z + xv.w * xv.w;
        r0 += q0 + q1;
        r1 += wz.x * q0 + wz.y * q1;
    }

    // Warp butterfly reduce both sums; every lane gets the totals.
#pragma unroll
    for (int o = 16; o; o >>= 1) {
        r0 += __shfl_xor_sync(0xffffffffu, r0, o);
        r1 += __shfl_xor_sync(0xffffffffu, r1, o);
    }

    const float n  = sqrtf(r0);
    const float s1 = atanhf(n) / fmaxf(n, 1e-12f);
    const float m  = s1 * sqrtf(r1);
    const float s  = s1 * tanhf(m) / fmaxf(m, 1e-12f);

    // Force pass 2 to genuinely reload x (L1/L2 hit) instead of keeping
    // 32 registers of x live across the reduction.
    asm volatile("" ::: "memory");

    // ── Pass 2: reload, rotate, scale, streaming-store.
#pragma unroll
    for (int j = 0; j < 8; ++j) {
        const float4 xv = xr[lane + 32 * j];
        const float4 w  = sW4[lane + 32 * j];
        float4 o4;
        o4.x = s * (w.x * xv.x - w.y * xv.y);
        o4.y = s * (w.x * xv.y + w.y * xv.x);
        o4.z = s * (w.z * xv.z - w.w * xv.w);
        o4.w = s * (w.z * xv.w + w.w * xv.z);
        __stcs(orow + lane + 32 * j, o4);   // evict-first: keep x in L2
    }
}

extern "C" void kernel_launch(void* const* d_in, const int* in_sizes, int n_in,
                              void* d_out, int out_size) {
    const float* x      = (const float*)d_in[0];
    const float* params = (const float*)d_in[1];
    float* out          = (float*)d_out;

    const int rows = in_sizes[0] / DIM;   // 32768
    hyper_butterfly_2pass<<<rows >> 3, 256>>>(x, params, out);
}